// round 3
// baseline (speedup 1.0000x reference)
#include <cuda_runtime.h>
#include <math.h>

#define NT 64      // targets
#define NA 3       // anchors per level
#define NCLS 80
#define NB 8       // batch

// Level geometry
#define H0 76
#define H1 38
#define H2 19
#define HW0 (H0*H0)   // 5776
#define HW1 (H1*H1)   // 1444
#define HW2 (H2*H2)   // 361

// Cells per level = B * A * HW
#define NC0 (NB*NA*HW0)   // 138624
#define NC1 (NB*NA*HW1)   // 34656
#define NC2 (NB*NA*HW2)   // 8664

#define TPB 256
#define NBK0 ((NC0 + TPB - 1)/TPB)   // 542
#define NBK1 ((NC1 + TPB - 1)/TPB)   // 136
#define NBK2 ((NC2 + TPB - 1)/TPB)   // 34
#define NGATHER (3*NT*NA)            // 576 warp tasks
#define NBKG (NGATHER/8)             // 72 blocks (8 warps each)
#define GRID (NBK0+NBK1+NBK2+NBKG)   // 784

#define IOU_THRESH 0.213f
#define IGNORE_THRESH 0.7f
#define COORD_SCALE 0.07f
#define FOUR_OVER_PI2 0.4052847345693511f

__device__ const float c_anch[3][3][2] = {
    {{1.5f, 2.0f}, {2.375f, 4.5f}, {5.0f, 3.5f}},
    {{2.25f, 4.6875f}, {4.75f, 3.4375f}, {4.5f, 9.125f}},
    {{4.4375f, 3.4375f}, {6.0f, 7.59375f}, {14.34375f, 12.53125f}}
};
__device__ const float c_xys[3] = {1.2f, 1.1f, 1.05f};
__device__ const float c_red[3] = {8.0f, 16.0f, 32.0f};
__device__ const int   c_H[3]  = {H0, H1, H2};
__device__ const int   c_HW[3] = {HW0, HW1, HW2};

// Per-(level, target) scratch, written by setup kernel
__device__ float g_tcx[3][NT], g_tcy[3][NT], g_tw[3][NT], g_th[3][NT];
__device__ int   g_ti[3][NT], g_tj[3][NT], g_tbid[3][NT], g_match[3][NT];

__device__ __forceinline__ float softplusf(float x) {
    // logaddexp(x, 0) = max(x,0) + log1p(exp(-|x|))
    return fmaxf(x, 0.0f) + log1pf(expf(-fabsf(x)));
}

// ---------------------------------------------------------------------------
// Kernel A: per-(level,target) preprocessing + zero accumulators
// ---------------------------------------------------------------------------
__global__ void setup_kernel(const float* __restrict__ targets, float* __restrict__ out) {
    int idx = threadIdx.x;          // 0..191
    if (idx < 3) out[idx] = 0.0f;
    if (idx >= 3 * NT) return;
    int l = idx / NT;
    int t = idx % NT;

    float red = c_red[l];
    float x1 = targets[t*5+0] / red;
    float y1 = targets[t*5+1] / red;
    float x2 = targets[t*5+2] / red;
    float y2 = targets[t*5+3] / red;
    int bid  = (int)targets[t*5+4];

    float w = x2 - x1, h = y2 - y1;
    float cx = (x1 + x2) * 0.5f, cy = (y1 + y2) * 0.5f;
    int ti = (int)cx, tj = (int)cy;

    g_tcx[l][t] = cx;  g_tcy[l][t] = cy;
    g_tw[l][t]  = w;   g_th[l][t]  = h;
    g_ti[l][t]  = ti;  g_tj[l][t]  = tj;
    g_tbid[l][t] = bid;

    // anchor-target IoU matching
    float ta = w * h;
    float ious[NA];
    float best = -1.0f; int bi = 0;
    #pragma unroll
    for (int a = 0; a < NA; a++) {
        float aw = c_anch[l][a][0], ah = c_anch[l][a][1];
        float inter = fminf(aw, w) * fminf(ah, h);
        float iou = inter / (aw*ah + ta - inter);
        ious[a] = iou;
        if (iou > best) { best = iou; bi = a; }   // first-max, matches argmax
    }
    int m = 0;
    #pragma unroll
    for (int a = 0; a < NA; a++)
        if (ious[a] > IOU_THRESH || a == bi) m |= (1 << a);
    g_match[l][t] = m;
}

// ---------------------------------------------------------------------------
// Kernel B: fused cell pass (obj_neg) + gather pass (ciou/obj_pos/cls)
// out[0]=iou_loss, out[1]=obj_loss, out[2]=cls_loss
// ---------------------------------------------------------------------------
__global__ void __launch_bounds__(TPB)
main_kernel(const float* __restrict__ p0, const float* __restrict__ p1,
            const float* __restrict__ p2, const int* __restrict__ cats,
            float* __restrict__ out) {
    int blk = blockIdx.x;

    if (blk < NBK0 + NBK1 + NBK2) {
        // ------------------ cell path: obj_neg ------------------
        int lvl, cell;
        if (blk < NBK0)              { lvl = 0; cell = blk * TPB + threadIdx.x; }
        else if (blk < NBK0 + NBK1)  { lvl = 1; cell = (blk - NBK0) * TPB + threadIdx.x; }
        else                         { lvl = 2; cell = (blk - NBK0 - NBK1) * TPB + threadIdx.x; }

        __shared__ float s_cx[NT], s_cy[NT], s_w[NT], s_h[NT];
        __shared__ int   s_ij[NT];   // ti | tj<<16
        __shared__ int   s_bm[NT];   // bid | match<<8
        __shared__ float s_wsum[TPB/32];

        if (threadIdx.x < NT) {
            int t = threadIdx.x;
            s_cx[t] = g_tcx[lvl][t];  s_cy[t] = g_tcy[lvl][t];
            s_w[t]  = g_tw[lvl][t];   s_h[t]  = g_th[lvl][t];
            s_ij[t] = g_ti[lvl][t] | (g_tj[lvl][t] << 16);
            s_bm[t] = g_tbid[lvl][t] | (g_match[lvl][t] << 8);
        }
        __syncthreads();

        int HW = c_HW[lvl];
        int Wd = c_H[lvl];
        const int NCl = NB * NA * HW;
        const float* pred = (lvl == 0) ? p0 : (lvl == 1) ? p1 : p2;

        float partial = 0.0f;
        if (cell < NCl) {
            int x = cell % Wd;
            int r = cell / Wd;
            int y = r % c_H[lvl]; r /= c_H[lvl];
            int a = r % NA;
            int b = r / NA;

            const float* pb = pred + (size_t)b * (NA*85) * HW + (size_t)(a*85) * HW + y * Wd + x;
            float px = pb[0], py = pb[HW], pw = pb[2*HW], ph = pb[3*HW], po = pb[4*HW];

            float xys = c_xys[lvl];
            float off = 0.5f * (xys - 1.0f);
            float bx = xys / (1.0f + expf(-px)) - off + (float)x;
            float by = xys / (1.0f + expf(-py)) - off + (float)y;
            float bw = expf(pw) * c_anch[lvl][a][0];
            float bh = expf(ph) * c_anch[lvl][a][1];
            float bx1 = bx - bw*0.5f, bx2 = bx + bw*0.5f;
            float by1 = by - bh*0.5f, by2 = by + bh*0.5f;
            float barea = bw * bh;

            bool dead = false;
            for (int t = 0; t < NT; t++) {
                int bm = s_bm[t];
                if ((bm & 0xff) != b) continue;   // warp-uniform: b constant in warp
                float tw = s_w[t], th = s_h[t], tcx = s_cx[t], tcy = s_cy[t];
                float ix = fminf(bx2, tcx + tw*0.5f) - fmaxf(bx1, tcx - tw*0.5f);
                float iy = fminf(by2, tcy + th*0.5f) - fmaxf(by1, tcy - th*0.5f);
                float inter = fmaxf(ix, 0.0f) * fmaxf(iy, 0.0f);
                float iou = inter / (barea + tw*th + 1e-16f - inter);
                if (iou > IGNORE_THRESH) dead = true;
                int ij = s_ij[t];
                if ((ij & 0xffff) == x && (ij >> 16) == y && ((bm >> (8 + a)) & 1)) dead = true;
            }
            if (!dead) partial = softplusf(po);
        }

        // block reduce -> single atomic
        #pragma unroll
        for (int o = 16; o > 0; o >>= 1)
            partial += __shfl_down_sync(0xffffffffu, partial, o);
        int lane = threadIdx.x & 31, warp = threadIdx.x >> 5;
        if (lane == 0) s_wsum[warp] = partial;
        __syncthreads();
        if (threadIdx.x == 0) {
            float s = 0.0f;
            #pragma unroll
            for (int i = 0; i < TPB/32; i++) s += s_wsum[i];
            atomicAdd(&out[1], s);
        }
    } else {
        // ------------------ gather path: ciou / obj_pos / cls ------------------
        int task = (blk - (NBK0 + NBK1 + NBK2)) * 8 + (threadIdx.x >> 5);
        int lane = threadIdx.x & 31;
        if (task >= NGATHER) return;
        int lvl = task / (NT * NA);
        int r   = task % (NT * NA);
        int a   = r / NT;
        int t   = r % NT;

        if (!((g_match[lvl][t] >> a) & 1)) return;  // every term multiplied by match

        int HW = c_HW[lvl];
        int Wd = c_H[lvl];
        const float* pred = (lvl == 0) ? p0 : (lvl == 1) ? p1 : p2;
        int bid = g_tbid[lvl][t];
        int ti  = g_ti[lvl][t], tj = g_tj[lvl][t];
        const float* pb = pred + (size_t)bid * (NA*85) * HW + (size_t)(a*85) * HW + tj * Wd + ti;

        // class BCE sum across warp
        int cat = cats[t] - 1;
        float cs = 0.0f;
        for (int k = lane; k < NCLS; k += 32) {
            float xv = pb[(size_t)(5 + k) * HW];
            cs += softplusf(xv) - ((k == cat) ? xv : 0.0f);
        }
        #pragma unroll
        for (int o = 16; o > 0; o >>= 1)
            cs += __shfl_down_sync(0xffffffffu, cs, o);

        if (lane == 0) {
            float px = pb[0], py = pb[HW], pw = pb[2*HW], ph = pb[3*HW], po = pb[4*HW];
            float obj_pos = softplusf(po) - po;   // bce(logit, 1)

            float xys = c_xys[lvl];
            float off = 0.5f * (xys - 1.0f);
            float bx = xys / (1.0f + expf(-px)) - off;
            float by = xys / (1.0f + expf(-py)) - off;
            float bw = expf(pw) * c_anch[lvl][a][0];
            float bh = expf(ph) * c_anch[lvl][a][1];

            float tx = g_tcx[lvl][t] - (float)ti;
            float ty = g_tcy[lvl][t] - (float)tj;
            float tw = g_tw[lvl][t],  th = g_th[lvl][t];

            float b1x1 = bx - bw*0.5f, b1x2 = bx + bw*0.5f;
            float b1y1 = by - bh*0.5f, b1y2 = by + bh*0.5f;
            float b2x1 = tx - tw*0.5f, b2x2 = tx + tw*0.5f;
            float b2y1 = ty - th*0.5f, b2y2 = ty + th*0.5f;

            float ix = fminf(b1x2, b2x2) - fmaxf(b1x1, b2x1);
            float iy = fminf(b1y2, b2y2) - fmaxf(b1y1, b2y1);
            float inter = fmaxf(ix, 0.0f) * fmaxf(iy, 0.0f);
            float uni = bw*bh + tw*th + 1e-16f - inter;
            float iou = inter / uni;

            float cw = fmaxf(b1x2, b2x2) - fminf(b1x1, b2x1);
            float ch = fmaxf(b1y2, b2y2) - fminf(b1y1, b2y1);
            float c2 = cw*cw + ch*ch + 1e-16f;
            float rho2 = (bx - tx)*(bx - tx) + (by - ty)*(by - ty);
            float dv = atanf(tw / th) - atanf(bw / bh);
            float v = FOUR_OVER_PI2 * dv * dv;
            float alpha = v / (1.0f - iou + v + 1e-16f);
            float ciou = iou - (rho2 / c2 + v * alpha);

            atomicAdd(&out[0], (1.0f - ciou) * COORD_SCALE);
            atomicAdd(&out[1], obj_pos);
            atomicAdd(&out[2], cs);
        }
    }
}

extern "C" void kernel_launch(void* const* d_in, const int* in_sizes, int n_in,
                              void* d_out, int out_size) {
    const float* p0      = (const float*)d_in[0];
    const float* p1      = (const float*)d_in[1];
    const float* p2      = (const float*)d_in[2];
    const float* targets = (const float*)d_in[3];
    const int*   cats    = (const int*)d_in[4];
    float* out = (float*)d_out;

    setup_kernel<<<1, 3 * NT>>>(targets, out);
    main_kernel<<<GRID, TPB>>>(p0, p1, p2, cats, out);
}

// round 5
// speedup vs baseline: 2.3304x; 2.3304x over previous
#include <cuda_runtime.h>
#include <math.h>

#define NT 64      // targets
#define NA 3       // anchors per level
#define NCLS 80
#define NB 8       // batch
#define TPB 256

#define H0 76
#define H1 38
#define H2 19
#define HW0 (H0*H0)
#define HW1 (H1*H1)
#define HW2 (H2*H2)
#define NC0 (NB*NA*HW0)   // 138624
#define NC1 (NB*NA*HW1)   // 34656
#define NC2 (NB*NA*HW2)   // 8664
#define NBK0 ((NC0+TPB-1)/TPB)   // 542
#define NBK1 ((NC1+TPB-1)/TPB)   // 136
#define NBK2 ((NC2+TPB-1)/TPB)   // 34
#define NCELLBK (NBK0+NBK1+NBK2) // 712
#define NBKG_PER_LVL (NT*NA/8)   // 24 gather blocks per level (8 warps each)
#define NBKG (3*NBKG_PER_LVL)    // 72
#define GRID (NCELLBK+NBKG)      // 784

#define IOU_T 0.213f
#define IGN_T 0.7f
#define COORD_SCALE 0.07f
#define FOUR_OVER_PI2 0.4052847345693511f

__constant__ float c_anch[3][3][2] = {
    {{1.5f, 2.0f}, {2.375f, 4.5f}, {5.0f, 3.5f}},
    {{2.25f, 4.6875f}, {4.75f, 3.4375f}, {4.5f, 9.125f}},
    {{4.4375f, 3.4375f}, {6.0f, 7.59375f}, {14.34375f, 12.53125f}}
};
__constant__ float c_invred[3] = {0.125f, 0.0625f, 0.03125f};
__constant__ float c_xysc[3]   = {1.2f, 1.1f, 1.05f};

// cross-block accumulators + ticket (zero at module load; reset by last block)
__device__ float g_acc[3];
__device__ int   g_ticket;

__device__ __forceinline__ float softplusf(float x) {
    return fmaxf(x, 0.0f) + __logf(1.0f + __expf(-fabsf(x)));
}

// ---------------------------------------------------------------------------
// Cell path (templated on level => constant div/mod, constant strides):
// returns softplus(obj) if this cell is a "negative", else 0.
// ---------------------------------------------------------------------------
template<int LVL>
__device__ __forceinline__ float cell_obj(const float* __restrict__ pred, int cell,
    const float4* __restrict__ s_box, const float2* __restrict__ s_meta,
    const int* __restrict__ s_start)
{
    constexpr int   Hd  = (LVL==0) ? H0 : (LVL==1) ? H1 : H2;
    constexpr int   HWc = Hd * Hd;
    constexpr float xys = (LVL==0) ? 1.2f : (LVL==1) ? 1.1f : 1.05f;
    constexpr float off = 0.5f * (xys - 1.0f);

    int x = cell % Hd;
    int r = cell / Hd;
    int y = r % Hd;  r /= Hd;
    int a = r % NA;
    int b = r / NA;

    const float* pb = pred + ((b*NA + a)*85)*HWc + y*Hd + x;
    float px = pb[0], py = pb[HWc], pw = pb[2*HWc], ph = pb[3*HWc], po = pb[4*HWc];

    float bx = __fdividef(xys, 1.0f + __expf(-px)) - off + (float)x;
    float by = __fdividef(xys, 1.0f + __expf(-py)) - off + (float)y;
    float bw = __expf(pw) * c_anch[LVL][a][0];
    float bh = __expf(ph) * c_anch[LVL][a][1];
    float bx1 = bx - bw*0.5f, bx2 = bx + bw*0.5f;
    float by1 = by - bh*0.5f, by2 = by + bh*0.5f;
    float rhs_c = IGN_T * (bw*bh + 1e-16f);   // IG*(barea + eps)

    int key = x | (y << 8);
    bool dead = false;
    int lo = s_start[b], hi = s_start[b+1];   // warp-uniform (b uniform in warp)
    for (int t = lo; t < hi; t++) {
        float4 tb = s_box[t];                 // corners: x1,y1,x2,y2 (smem broadcast)
        float2 tm = s_meta[t];                // (area, packed meta)
        float ix = fminf(bx2, tb.z) - fmaxf(bx1, tb.x);
        float iy = fminf(by2, tb.w) - fmaxf(by1, tb.y);
        float inter = fmaxf(ix, 0.0f) * fmaxf(iy, 0.0f);
        // iou > IG  <=>  inter*(1+IG) > IG*(barea + tarea + eps)   (union > 0)
        bool c1 = inter * (1.0f + IGN_T) > fmaf(IGN_T, tm.x, rhs_c);
        int mm = __float_as_int(tm.y);        // ti | tj<<8 | match<<16
        bool c2 = ((mm & 0xffff) == key) && (((mm >> (16 + a)) & 1) != 0);
        dead = dead | c1 | c2;
    }
    return dead ? 0.0f : softplusf(po);
}

// ---------------------------------------------------------------------------
// Single fused kernel. Block roles:
//   [0, NCELLBK): cell blocks (obj_neg), level by range, targets bucketed by bid
//   [NCELLBK, GRID): gather blocks, 8 warps = 8 (anchor,target) tasks, 1 level/block
// Last block (ticket) writes out[0..2] and resets accumulators.
// ---------------------------------------------------------------------------
__global__ void __launch_bounds__(TPB)
yolo_kernel(const float* __restrict__ p0, const float* __restrict__ p1,
            const float* __restrict__ p2, const float* __restrict__ targets,
            const int* __restrict__ cats, float* __restrict__ out)
{
    __shared__ float  s_raw[NT*5];
    __shared__ float4 s_box[NT];
    __shared__ float2 s_meta[NT];
    __shared__ int    s_gm[NT];
    __shared__ int    s_start[NB+1];
    __shared__ int    s_off[NB];
    __shared__ float  s_warp[TPB/32];
    __shared__ float  s_acc[3];
    __shared__ bool   s_last;

    int tid = threadIdx.x;
    int blk = blockIdx.x;

    bool is_cell = blk < NCELLBK;
    int lvl, cellbase = 0;
    if (blk < NBK0)           { lvl = 0; cellbase = blk*TPB; }
    else if (blk < NBK0+NBK1) { lvl = 1; cellbase = (blk-NBK0)*TPB; }
    else if (blk < NCELLBK)   { lvl = 2; cellbase = (blk-NBK0-NBK1)*TPB; }
    else                      { lvl = (blk-NCELLBK)/NBKG_PER_LVL; }

    // stage raw targets into smem (coalesced)
    for (int i = tid; i < NT*5; i += TPB) s_raw[i] = targets[i];
    if (tid < NB+1) s_start[tid] = 0;
    if (tid < 3)    s_acc[tid] = 0.0f;
    __syncthreads();

    // per-target preprocessing (threads 0..63)
    float cx = 0.f, cy = 0.f, w = 0.f, h = 0.f;
    int bid = 0, ti = 0, tj = 0, match = 0;
    if (tid < NT) {
        float ir = c_invred[lvl];
        float x1 = s_raw[tid*5+0]*ir, y1 = s_raw[tid*5+1]*ir;
        float x2 = s_raw[tid*5+2]*ir, y2 = s_raw[tid*5+3]*ir;
        bid = (int)s_raw[tid*5+4];
        w = x2 - x1;  h = y2 - y1;
        cx = (x1 + x2)*0.5f;  cy = (y1 + y2)*0.5f;
        ti = (int)cx;  tj = (int)cy;
        float ta = w*h;
        float ious[NA]; float best = -1.0f; int bi = 0;
        #pragma unroll
        for (int a = 0; a < NA; a++) {
            float aw = c_anch[lvl][a][0], ah = c_anch[lvl][a][1];
            float inter = fminf(aw, w) * fminf(ah, h);
            float iou = inter / (aw*ah + ta - inter);
            ious[a] = iou;
            if (iou > best) { best = iou; bi = a; }   // first-max == argmax
        }
        #pragma unroll
        for (int a = 0; a < NA; a++)
            if (ious[a] > IOU_T || a == bi) match |= 1 << a;
    }

    if (is_cell) {
        // counting sort by batch-id into smem buckets
        if (tid < NT) atomicAdd(&s_start[bid+1], 1);
        __syncthreads();
        if (tid == 0) {
            #pragma unroll
            for (int i = 1; i <= NB; i++) s_start[i] += s_start[i-1];
        }
        __syncthreads();
        if (tid < NB) s_off[tid] = s_start[tid];
        __syncthreads();
        if (tid < NT) {
            int pos = atomicAdd(&s_off[bid], 1);
            s_box[pos]  = make_float4(cx - w*0.5f, cy - h*0.5f, cx + w*0.5f, cy + h*0.5f);
            s_meta[pos] = make_float2(w*h, __int_as_float(ti | (tj<<8) | (match<<16)));
        }
        __syncthreads();

        int cell = cellbase + tid;
        float partial = 0.0f;
        if (lvl == 0)      { if (cell < NC0) partial = cell_obj<0>(p0, cell, s_box, s_meta, s_start); }
        else if (lvl == 1) { if (cell < NC1) partial = cell_obj<1>(p1, cell, s_box, s_meta, s_start); }
        else               { if (cell < NC2) partial = cell_obj<2>(p2, cell, s_box, s_meta, s_start); }

        #pragma unroll
        for (int o = 16; o > 0; o >>= 1)
            partial += __shfl_down_sync(0xffffffffu, partial, o);
        if ((tid & 31) == 0) s_warp[tid >> 5] = partial;
        __syncthreads();
        if (tid == 0) {
            float s = 0.0f;
            #pragma unroll
            for (int i = 0; i < TPB/32; i++) s += s_warp[i];
            atomicAdd(&g_acc[1], s);
        }
    } else {
        // gather path: publish per-target data (unsorted)
        if (tid < NT) {
            s_box[tid] = make_float4(cx, cy, w, h);
            s_gm[tid]  = ti | (tj << 8) | (match << 16) | (bid << 19);
        }
        __syncthreads();

        int warp = tid >> 5, lane = tid & 31;
        int r = ((blk - NCELLBK) % NBKG_PER_LVL) * 8 + warp;  // 0..191
        int a = r / NT, t = r % NT;
        int gm = s_gm[t];
        if ((gm >> (16 + a)) & 1) {
            const float* pred = (lvl==0) ? p0 : (lvl==1) ? p1 : p2;
            int HW = (lvl==0) ? HW0 : (lvl==1) ? HW1 : HW2;
            int Wd = (lvl==0) ? H0  : (lvl==1) ? H1  : H2;
            int tbid = (gm >> 19) & 7, tti = gm & 255, ttj = (gm >> 8) & 255;
            const float* pb = pred + ((tbid*NA + a)*85)*HW + ttj*Wd + tti;

            int cat = cats[t] - 1;
            float cs = 0.0f;
            for (int k = lane; k < NCLS; k += 32) {
                float xv = pb[(5 + k)*HW];
                cs += softplusf(xv) - ((k == cat) ? xv : 0.0f);
            }
            #pragma unroll
            for (int o = 16; o > 0; o >>= 1)
                cs += __shfl_down_sync(0xffffffffu, cs, o);

            if (lane == 0) {
                float4 tb = s_box[t];
                float px = pb[0], py = pb[HW], pw = pb[2*HW], ph = pb[3*HW], po = pb[4*HW];
                float obj_pos = softplusf(po) - po;          // bce(logit, 1)

                float xys = c_xysc[lvl];
                float off = 0.5f * (xys - 1.0f);
                float bx = __fdividef(xys, 1.0f + __expf(-px)) - off;
                float by = __fdividef(xys, 1.0f + __expf(-py)) - off;
                float bw = __expf(pw) * c_anch[lvl][a][0];
                float bh = __expf(ph) * c_anch[lvl][a][1];

                float tx = tb.x - (float)tti, ty = tb.y - (float)ttj;
                float tw = tb.z, th = tb.w;

                float b1x1 = bx - bw*0.5f, b1x2 = bx + bw*0.5f;
                float b1y1 = by - bh*0.5f, b1y2 = by + bh*0.5f;
                float b2x1 = tx - tw*0.5f, b2x2 = tx + tw*0.5f;
                float b2y1 = ty - th*0.5f, b2y2 = ty + th*0.5f;

                float ix = fminf(b1x2, b2x2) - fmaxf(b1x1, b2x1);
                float iy = fminf(b1y2, b2y2) - fmaxf(b1y1, b2y1);
                float inter = fmaxf(ix, 0.0f) * fmaxf(iy, 0.0f);
                float uni = bw*bh + tw*th + 1e-16f - inter;
                float iou = inter / uni;

                float cw = fmaxf(b1x2, b2x2) - fminf(b1x1, b2x1);
                float ch = fmaxf(b1y2, b2y2) - fminf(b1y1, b2y1);
                float c2 = cw*cw + ch*ch + 1e-16f;
                float rho2 = (bx - tx)*(bx - tx) + (by - ty)*(by - ty);
                float dv = atanf(tw / th) - atanf(bw / bh);
                float v = FOUR_OVER_PI2 * dv * dv;
                float alpha = v / (1.0f - iou + v + 1e-16f);
                float ciou = iou - (rho2 / c2 + v * alpha);

                atomicAdd(&s_acc[0], (1.0f - ciou) * COORD_SCALE);
                atomicAdd(&s_acc[1], obj_pos);
                atomicAdd(&s_acc[2], cs);
            }
        }
        __syncthreads();
        if (tid == 0) {
            atomicAdd(&g_acc[0], s_acc[0]);
            atomicAdd(&g_acc[1], s_acc[1]);
            atomicAdd(&g_acc[2], s_acc[2]);
        }
    }

    // ---- last-block finalize: write out, reset accumulators for next replay ----
    if (tid == 0) {
        __threadfence();
        int tk = atomicAdd(&g_ticket, 1);
        s_last = (tk == GRID - 1);
    }
    __syncthreads();
    if (s_last && tid == 0) {
        __threadfence();
        volatile float* ga = g_acc;
        out[0] = ga[0];  out[1] = ga[1];  out[2] = ga[2];
        ga[0] = 0.0f;  ga[1] = 0.0f;  ga[2] = 0.0f;
        g_ticket = 0;
    }
}

extern "C" void kernel_launch(void* const* d_in, const int* in_sizes, int n_in,
                              void* d_out, int out_size) {
    const float* p0      = (const float*)d_in[0];
    const float* p1      = (const float*)d_in[1];
    const float* p2      = (const float*)d_in[2];
    const float* targets = (const float*)d_in[3];
    const int*   cats    = (const int*)d_in[4];
    float* out = (float*)d_out;

    yolo_kernel<<<GRID, TPB>>>(p0, p1, p2, targets, cats, out);
}